// round 5
// baseline (speedup 1.0000x reference)
#include <cuda_runtime.h>

// Operator3D: bs=4, v=8192, n=20, SUPPORT=4, KERNEL=32  (S*K = 128)
// inputs: [0] neighbor_index int32 (bs,v,n)
//         [1] vertices       f32   (bs,v,3)
//         [2] weights        f32   (1,1,4,32)
//         [3] displacement   f32   (3,128)
// output: feature f32 (bs,v,32)
//
// One warp per row (lane = kernel channel k), grid-stride, single wave
// (740 = 5 blocks/SM * 148 SMs, matching reg-limited residency).
// Inner loop packs the 4 support dims pairwise into f32x2 ops:
//   t01 = (theta_s0, theta_s1), t23 = (theta_s2, theta_s3)
// Matrix pairs (6 u64 = 12 regs, no duplication cost); the per-neighbor
// displacement is duplicated (d,d) in SMEM and loaded as b64 pairs, so no
// pack/unpack ALU work in the hot loop.

#define BS_   4
#define V_    8192
#define N_    20
#define K_    32
#define SK_   128
#define ROWS_ (BS_ * V_)

#define WPB      8
#define THREADS_ (WPB * 32)
#define BLOCKS_  740                 // 5 blocks/SM * 148 -> one full wave
#define NWARPS_  (BLOCKS_ * WPB)     // 5920 warps, ~5.5 rows each

typedef unsigned long long u64;

__device__ __forceinline__ u64 packf2(float lo, float hi) {
    u64 r;
    asm("mov.b64 %0, {%1, %2};" : "=l"(r) : "f"(lo), "f"(hi));
    return r;
}
__device__ __forceinline__ void unpackf2(float& lo, float& hi, u64 v) {
    asm("mov.b64 {%0, %1}, %2;" : "=f"(lo), "=f"(hi) : "l"(v));
}
#define FMA_F32X2(out, a, b, c) \
    asm("fma.rn.f32x2 %0, %1, %2, %3;" : "=l"(out) : "l"(a), "l"(b), "l"(c))
#define MUL_F32X2_(out, a, b) \
    asm("mul.rn.f32x2 %0, %1, %2;" : "=l"(out) : "l"(a), "l"(b))

// 32B per neighbor: (dx,dx) (dy,dy) (dz,dz) pad — 16B-aligned for v2.b64
struct __align__(16) Nbr { u64 x2, y2, z2, pad; };

__global__ __launch_bounds__(THREADS_)
void op3d_kernel(const int*   __restrict__ nb,
                 const float* __restrict__ verts,
                 const float* __restrict__ weights,
                 const float* __restrict__ disp,
                 float*       __restrict__ out)
{
    __shared__ Nbr sd[WPB][N_];

    const int warp  = threadIdx.x >> 5;
    const int lane  = threadIdx.x & 31;
    const int gwarp = blockIdx.x * WPB + warp;

    // Support-paired displacement-matrix columns: 6 u64 = 12 regs (no dup).
    const u64 D0_01 = packf2(disp[0*SK_ +  0 + lane], disp[0*SK_ + 32 + lane]);
    const u64 D0_23 = packf2(disp[0*SK_ + 64 + lane], disp[0*SK_ + 96 + lane]);
    const u64 D1_01 = packf2(disp[1*SK_ +  0 + lane], disp[1*SK_ + 32 + lane]);
    const u64 D1_23 = packf2(disp[1*SK_ + 64 + lane], disp[1*SK_ + 96 + lane]);
    const u64 D2_01 = packf2(disp[2*SK_ +  0 + lane], disp[2*SK_ + 32 + lane]);
    const u64 D2_23 = packf2(disp[2*SK_ + 64 + lane], disp[2*SK_ + 96 + lane]);
    const float w0 = weights[ 0 + lane];
    const float w1 = weights[32 + lane];
    const float w2 = weights[64 + lane];
    const float w3 = weights[96 + lane];

    // shared-space addresses (32-bit) for this warp's buffer
    const unsigned sbase =
        (unsigned)__cvta_generic_to_shared(&sd[warp][0]);
    const unsigned smine = sbase + (unsigned)(lane & 31) * sizeof(Nbr);

    for (int r = gwarp; r < ROWS_; r += NWARPS_) {
        const int b     = r >> 13;            // r / V_
        const int vbase = b * (V_ * 3);

        if (lane < N_) {
            const int idx = nb[r * N_ + lane];
            const float* p = verts + vbase + idx * 3;
            const float* q = verts + r * 3;           // broadcast, L1 hit
            const u64 x2 = packf2(p[0] - q[0], p[0] - q[0]);
            const u64 y2 = packf2(p[1] - q[1], p[1] - q[1]);
            const u64 z2 = packf2(p[2] - q[2], p[2] - q[2]);
            asm volatile("st.shared.v2.b64 [%0], {%1, %2};"
                         :: "r"(smine), "l"(x2), "l"(y2));
            asm volatile("st.shared.b64 [%0], %1;"
                         :: "r"(smine + 16), "l"(z2));
        }
        __syncwarp();

        // running max seeded at 0 == relu(max_n theta)
        float m0 = 0.0f, m1 = 0.0f, m2 = 0.0f, m3 = 0.0f;
        #pragma unroll
        for (int j = 0; j < N_; j++) {
            u64 x2, y2, z2;
            const unsigned a = sbase + j * (unsigned)sizeof(Nbr);
            asm("ld.shared.v2.b64 {%0, %1}, [%2];"
                : "=l"(x2), "=l"(y2) : "r"(a));
            asm("ld.shared.b64 %0, [%1];"
                : "=l"(z2) : "r"(a + 16));

            u64 t01, t23;
            MUL_F32X2_(t01, z2, D2_01);
            FMA_F32X2(t01, y2, D1_01, t01);
            FMA_F32X2(t01, x2, D0_01, t01);
            MUL_F32X2_(t23, z2, D2_23);
            FMA_F32X2(t23, y2, D1_23, t23);
            FMA_F32X2(t23, x2, D0_23, t23);

            float t0, t1, t2, t3;
            unpackf2(t0, t1, t01);
            unpackf2(t2, t3, t23);
            m0 = fmaxf(m0, t0);
            m1 = fmaxf(m1, t1);
            m2 = fmaxf(m2, t2);
            m3 = fmaxf(m3, t3);
        }

        out[r * K_ + lane] = fmaf(m0, w0, fmaf(m1, w1, fmaf(m2, w2, m3 * w3)));
        __syncwarp();   // protect smem before next iteration's stores
    }
}

extern "C" void kernel_launch(void* const* d_in, const int* in_sizes, int n_in,
                              void* d_out, int out_size)
{
    const int*   nb      = (const int*)  d_in[0];
    const float* verts   = (const float*)d_in[1];
    const float* weights = (const float*)d_in[2];
    const float* disp    = (const float*)d_in[3];
    float*       out     = (float*)      d_out;

    op3d_kernel<<<BLOCKS_, THREADS_>>>(nb, verts, weights, disp, out);
}